// round 8
// baseline (speedup 1.0000x reference)
#include <cuda_runtime.h>
#include <cuda_bf16.h>

// One-hop neighbor sampling with replacement (EdgeSampler), float32 output.
// Geometry: NUM_NODES=1e6, B=256, R=512, S=16 -> 131072 seeds, SEC=2097152.
// Output layout (validated rel_err=0 in R6/R7): float32 [src|tgt|valid], SEC each.
//
// R8: R6 structure (1 quad/thread, max occupancy) with minimal instruction
// count: 3 pre-offset section pointers, 32-bit indexing, no store guards,
// no dead clamps. Latency-hiding comes from warp count, not per-thread MLP.

#define N_SEEDS   131072
#define N_THREADS (N_SEEDS * 4)       // 524288 quads
#define SEC       (N_SEEDS * 16)      // 2097152 floats per section

__global__ __launch_bounds__(256) void edge_sampler_kernel(
    const int*    __restrict__ seeds,
    const int*    __restrict__ rowp,
    const int*    __restrict__ col,
    const float4* __restrict__ rnd,     // [N_THREADS]
    float4* __restrict__ out_src,       // [N_THREADS]
    float4* __restrict__ out_tgt,       // [N_THREADS]
    float4* __restrict__ out_val,       // [N_THREADS]
    int row_max_idx)
{
    const unsigned u = blockIdx.x * 256u + threadIdx.x;   // < N_THREADS by grid
    const unsigned t = u >> 2;                            // seed index

    // Stage 1: seed (streaming, coalesced)
    const int sid = __ldg(&seeds[t]);
    const int c   = min(max(sid, 0), row_max_idx);

    // Stage 2: row_ptr pair (random, L2-resident 4MB) + rand (independent)
    const int    s = __ldg(&rowp[c]);
    const int    e = __ldg(&rowp[c + 1]);
    const float4 r = __ldg(&rnd[u]);

    const int   d  = e - s;
    const float df = (float)d;
    const int   cl = max(d - 1, 0);
    const bool  vb = (d > 0);

    // Gather positions: idx = (int)(u*deg) is >= 0 by construction; clamp high only.
    // pos = 0 for deg==0 (reference gathers col[0] there too).
    int p0 = vb ? s + min((int)(r.x * df), cl) : 0;
    int p1 = vb ? s + min((int)(r.y * df), cl) : 0;
    int p2 = vb ? s + min((int)(r.z * df), cl) : 0;
    int p3 = vb ? s + min((int)(r.w * df), cl) : 0;

    // Stage 3: four independent gathers
    const int g0 = __ldg(&col[p0]);
    const int g1 = __ldg(&col[p1]);
    const int g2 = __ldg(&col[p2]);
    const int g3 = __ldg(&col[p3]);

    // Stores: one float4 per section, fully coalesced.
    const float sf = (float)sid;
    const float vf = vb ? 1.0f : 0.0f;
    out_src[u] = make_float4(sf, sf, sf, sf);
    out_tgt[u] = make_float4((float)g0, (float)g1, (float)g2, (float)g3);
    out_val[u] = make_float4(vf, vf, vf, vf);
}

extern "C" void kernel_launch(void* const* d_in, const int* in_sizes, int n_in,
                              void* d_out, int out_size)
{
    // ---- Bind inputs by size ratios (order- and unit-invariant) ----
    int idx_seed = 0;
    for (int i = 1; i < n_in; i++)
        if (in_sizes[i] < in_sizes[idx_seed]) idx_seed = i;

    int idx_col = 0;
    for (int i = 1; i < n_in; i++)
        if (in_sizes[i] > in_sizes[idx_col]) idx_col = i;

    int idx_rand = -1;
    for (int i = 0; i < n_in; i++) {
        if (i != idx_seed && i != idx_col &&
            (long long)in_sizes[i] == 16LL * (long long)in_sizes[idx_seed]) {
            idx_rand = i; break;
        }
    }
    int idx_row = -1;
    for (int i = 0; i < n_in; i++)
        if (i != idx_seed && i != idx_col && i != idx_rand) { idx_row = i; break; }
    if (idx_rand < 0) idx_rand = idx_row;

    const int*    seeds = (const int*)d_in[idx_seed];
    const int*    rowp  = (const int*)d_in[idx_row];
    const int*    col   = (const int*)d_in[idx_col];
    const float4* rnd   = (const float4*)d_in[idx_rand];

    int row_max_idx = in_sizes[idx_row] - 2;
    if (row_max_idx < 0) row_max_idx = 0;

    float* out = (float*)d_out;
    float4* out_src = (float4*)(out);
    float4* out_tgt = (float4*)(out + SEC);
    float4* out_val = (float4*)(out + 2 * SEC);

    const int threads = 256;
    const int blocks  = N_THREADS / threads;   // 2048
    edge_sampler_kernel<<<blocks, threads>>>(
        seeds, rowp, col, rnd, out_src, out_tgt, out_val, row_max_idx);
}